// round 13
// baseline (speedup 1.0000x reference)
#include <cuda_runtime.h>
#include <cuda_fp16.h>
#include <cstdint>

#define N_NODES 100000
#define N_EDGES 1600000
#define DIM     128
#define ALPHA   4

#define SCAN_BLK   1024
#define SCAN_ELEMS 2048
#define NB ((N_NODES + SCAN_ELEMS - 1) / SCAN_ELEMS)   // 49

// ---------------- scratch (device globals; no allocations allowed) ----------
__device__ __half             g_hwh[(size_t)N_NODES * DIM];   // h @ W.T (fp16)
__device__ unsigned long long g_degpack[ALPHA * N_NODES];     // count<<40 | fx24 deg
__device__ float              g_dinv[ALPHA * N_NODES];
__device__ int                g_cnt[ALPHA * N_NODES];
__device__ int                g_off[ALPHA * (N_NODES + 1)];
__device__ int                g_cursor[ALPHA * N_NODES];
__device__ int                g_bsum[ALPHA * NB];
__device__ int2               g_epack[(size_t)ALPHA * N_EDGES];  // {src row, norm bits}

// ============================================================================
// TF32 3-pass GEMM via mma.sync. out[r][n] = act(sum_k in[r][k]*W[n][k] (+b))
// out_half=0: write fp32 to out. out_half=1: write fp16 to (half*)out.
// ============================================================================
#define TILE_M   128
#define GT       256
#define LDA      132

__device__ __forceinline__ uint32_t f2tf32(float x) {
    uint32_t r;
    asm("cvt.rna.tf32.f32 %0, %1;" : "=r"(r) : "f"(x));
    return r;
}

__device__ __forceinline__ void mma_tf32(float c[4],
                                         uint32_t a0, uint32_t a1, uint32_t a2, uint32_t a3,
                                         uint32_t b0, uint32_t b1) {
    asm volatile(
        "mma.sync.aligned.m16n8k8.row.col.f32.tf32.tf32.f32 "
        "{%0,%1,%2,%3}, {%4,%5,%6,%7}, {%8,%9}, {%0,%1,%2,%3};"
        : "+f"(c[0]), "+f"(c[1]), "+f"(c[2]), "+f"(c[3])
        : "r"(a0), "r"(a1), "r"(a2), "r"(a3), "r"(b0), "r"(b1));
}

__global__ void __launch_bounds__(GT, 1)
gemm_mma(const float* __restrict__ in, const float* __restrict__ W,
         const float* __restrict__ bias, void* __restrict__ out,
         int n_rows, int do_relu, int out_half)
{
    extern __shared__ float smem[];
    float* As = smem;
    float* Ws = smem + TILE_M * LDA;

    const int tid  = threadIdx.x;
    const int wid  = tid >> 5;
    const int lane = tid & 31;
    const int gid  = lane >> 2;
    const int tig  = lane & 3;
    const int wm   = wid & 3;
    const int wn   = wid >> 2;
    const int row0 = blockIdx.x * TILE_M;

    const float4* in4 = (const float4*)in;
    #pragma unroll
    for (int i = 0; i < (TILE_M * 32) / GT; i++) {
        int idx = tid + i * GT;
        int r   = idx >> 5;
        int c4  = idx & 31;
        int row = row0 + r;
        float4 v = make_float4(0.f, 0.f, 0.f, 0.f);
        if (row < n_rows) v = in4[(size_t)row * 32 + c4];
        *(float4*)&As[r * LDA + c4 * 4] = v;
    }
    const float4* W4 = (const float4*)W;
    #pragma unroll
    for (int i = 0; i < (DIM * 32) / GT; i++) {
        int idx = tid + i * GT;
        int r   = idx >> 5;
        int c4  = idx & 31;
        *(float4*)&Ws[r * LDA + c4 * 4] = W4[(size_t)r * 32 + c4];
    }
    __syncthreads();

    float c[2][8][4];
    #pragma unroll
    for (int mi = 0; mi < 2; mi++)
        #pragma unroll
        for (int ni = 0; ni < 8; ni++)
            #pragma unroll
            for (int j = 0; j < 4; j++)
                c[mi][ni][j] = 0.f;

    #pragma unroll
    for (int ks = 0; ks < DIM / 8; ks++) {
        const int k0 = ks * 8;

        uint32_t ah[2][4], al[2][4];
        #pragma unroll
        for (int mi = 0; mi < 2; mi++) {
            const int rb = wm * 32 + mi * 16;
            float v0 = As[(rb + gid)     * LDA + k0 + tig];
            float v1 = As[(rb + gid + 8) * LDA + k0 + tig];
            float v2 = As[(rb + gid)     * LDA + k0 + tig + 4];
            float v3 = As[(rb + gid + 8) * LDA + k0 + tig + 4];
            ah[mi][0] = f2tf32(v0); al[mi][0] = f2tf32(v0 - __uint_as_float(ah[mi][0]));
            ah[mi][1] = f2tf32(v1); al[mi][1] = f2tf32(v1 - __uint_as_float(ah[mi][1]));
            ah[mi][2] = f2tf32(v2); al[mi][2] = f2tf32(v2 - __uint_as_float(ah[mi][2]));
            ah[mi][3] = f2tf32(v3); al[mi][3] = f2tf32(v3 - __uint_as_float(ah[mi][3]));
        }
        uint32_t bh[8][2], bl[8][2];
        #pragma unroll
        for (int ni = 0; ni < 8; ni++) {
            const int col = wn * 64 + ni * 8 + gid;
            float v0 = Ws[col * LDA + k0 + tig];
            float v1 = Ws[col * LDA + k0 + tig + 4];
            bh[ni][0] = f2tf32(v0); bl[ni][0] = f2tf32(v0 - __uint_as_float(bh[ni][0]));
            bh[ni][1] = f2tf32(v1); bl[ni][1] = f2tf32(v1 - __uint_as_float(bh[ni][1]));
        }

        #pragma unroll
        for (int mi = 0; mi < 2; mi++)
            #pragma unroll
            for (int ni = 0; ni < 8; ni++) {
                mma_tf32(c[mi][ni], ah[mi][0], ah[mi][1], ah[mi][2], ah[mi][3],
                         bh[ni][0], bh[ni][1]);
                mma_tf32(c[mi][ni], al[mi][0], al[mi][1], al[mi][2], al[mi][3],
                         bh[ni][0], bh[ni][1]);
                mma_tf32(c[mi][ni], ah[mi][0], ah[mi][1], ah[mi][2], ah[mi][3],
                         bl[ni][0], bl[ni][1]);
            }
    }
    __syncthreads();

    float* stage = As;
    #pragma unroll
    for (int mi = 0; mi < 2; mi++) {
        const int rb = wm * 32 + mi * 16;
        #pragma unroll
        for (int ni = 0; ni < 8; ni++) {
            const int cb = wn * 64 + ni * 8 + tig * 2;
            *(float2*)&stage[(rb + gid)     * LDA + cb] = make_float2(c[mi][ni][0], c[mi][ni][1]);
            *(float2*)&stage[(rb + gid + 8) * LDA + cb] = make_float2(c[mi][ni][2], c[mi][ni][3]);
        }
    }
    __syncthreads();

    #pragma unroll
    for (int i = 0; i < (TILE_M * 32) / GT; i++) {
        int idx = tid + i * GT;
        int r   = idx >> 5;
        int c4  = idx & 31;
        int row = row0 + r;
        if (row < n_rows) {
            float4 v = *(float4*)&stage[r * LDA + c4 * 4];
            if (bias) {
                const float4 b = *(const float4*)&bias[c4 * 4];
                v.x += b.x; v.y += b.y; v.z += b.z; v.w += b.w;
            }
            if (do_relu) {
                v.x = fmaxf(v.x, 0.f); v.y = fmaxf(v.y, 0.f);
                v.z = fmaxf(v.z, 0.f); v.w = fmaxf(v.w, 0.f);
            }
            if (out_half) {
                __half2 h0 = __floats2half2_rn(v.x, v.y);
                __half2 h1 = __floats2half2_rn(v.z, v.w);
                uint2 u = make_uint2(*(uint32_t*)&h0, *(uint32_t*)&h1);
                ((uint2*)out)[(size_t)row * 32 + c4] = u;
            } else {
                ((float4*)out)[(size_t)row * 32 + c4] = v;
            }
        }
    }
}

// ============================================================================
// batched per-layer graph prep (all ALPHA layers at once)
// ============================================================================
__global__ void clear_kernel()
{
    int i = blockIdx.x * blockDim.x + threadIdx.x;
    if (i < ALPHA * N_NODES) g_degpack[i] = 0ULL;
}

__global__ void deg_kernel(const int* __restrict__ eidx, const float* __restrict__ eattr)
{
    int e = blockIdx.x * blockDim.x + threadIdx.x;
    int l = blockIdx.y;
    if (e >= N_EDGES) return;
    int   c = eidx[(size_t)l * 2 * N_EDGES + N_EDGES + e];
    float a = eattr[(size_t)l * N_EDGES + e];
    unsigned long long add =
        (1ULL << 40) | (unsigned long long)(unsigned int)__float2uint_rn(a * 16777216.f);
    atomicAdd(&g_degpack[l * N_NODES + c], add);
}

__global__ void dinv_kernel()
{
    int i = blockIdx.x * blockDim.x + threadIdx.x;
    if (i < ALPHA * N_NODES) {
        unsigned long long v = g_degpack[i];
        int   cnt = (int)(v >> 40);
        float d   = (float)(v & 0xFFFFFFFFFFULL) * (1.f / 16777216.f);
        g_cnt[i]  = cnt;
        g_dinv[i] = (d > 0.f) ? rsqrtf(d) : 0.f;
    }
}

__global__ void scan_p1()
{
    const int l = blockIdx.y, b = blockIdx.x, tid = threadIdx.x;
    const int i0 = b * SCAN_ELEMS + tid * 2;
    int s = 0;
    if (i0     < N_NODES) s += g_cnt[l * N_NODES + i0];
    if (i0 + 1 < N_NODES) s += g_cnt[l * N_NODES + i0 + 1];

    __shared__ int sh[SCAN_BLK];
    sh[tid] = s;
    __syncthreads();
    #pragma unroll
    for (int ofs = SCAN_BLK / 2; ofs > 0; ofs >>= 1) {
        if (tid < ofs) sh[tid] += sh[tid + ofs];
        __syncthreads();
    }
    if (tid == 0) g_bsum[l * NB + b] = sh[0];
}

__global__ void scan_p2()
{
    int l = threadIdx.x;
    if (l < ALPHA) {
        int run = 0;
        for (int b = 0; b < NB; b++) {
            int v = g_bsum[l * NB + b];
            g_bsum[l * NB + b] = run;
            run += v;
        }
    }
}

__global__ void scan_p3()
{
    const int l = blockIdx.y, b = blockIdx.x, tid = threadIdx.x;
    const int i0 = b * SCAN_ELEMS + tid * 2;
    int v0 = 0, v1 = 0;
    if (i0     < N_NODES) v0 = g_cnt[l * N_NODES + i0];
    if (i0 + 1 < N_NODES) v1 = g_cnt[l * N_NODES + i0 + 1];
    const int tsum = v0 + v1;

    __shared__ int sh[SCAN_BLK];
    sh[tid] = tsum;
    __syncthreads();
    #pragma unroll
    for (int ofs = 1; ofs < SCAN_BLK; ofs <<= 1) {
        int x = (tid >= ofs) ? sh[tid - ofs] : 0;
        __syncthreads();
        sh[tid] += x;
        __syncthreads();
    }
    const int texcl = sh[tid] - tsum + g_bsum[l * NB + b];
    if (i0 < N_NODES) {
        g_off[l * (N_NODES + 1) + i0] = texcl;
        g_cursor[l * N_NODES + i0]    = texcl;
    }
    if (i0 + 1 < N_NODES) {
        g_off[l * (N_NODES + 1) + i0 + 1] = texcl + v0;
        g_cursor[l * N_NODES + i0 + 1]    = texcl + v0;
    }
    if (b == NB - 1 && tid == SCAN_BLK - 1)
        g_off[l * (N_NODES + 1) + N_NODES] = texcl + tsum;
}

__global__ void bin_kernel(const int* __restrict__ eidx, const float* __restrict__ eattr)
{
    int e = blockIdx.x * blockDim.x + threadIdx.x;
    int l = blockIdx.y;
    if (e >= N_EDGES) return;
    int r = eidx[(size_t)l * 2 * N_EDGES + e];
    int c = eidx[(size_t)l * 2 * N_EDGES + N_EDGES + e];
    int p = atomicAdd(&g_cursor[l * N_NODES + c], 1);
    float norm = g_dinv[l * N_NODES + r] * eattr[(size_t)l * N_EDGES + e]
               * g_dinv[l * N_NODES + c];
    g_epack[(size_t)l * N_EDGES + p] = make_int2(r, __float_as_int(norm));
}

// one warp per destination node; fp16 rows (256B), x4 unroll, fp32 accum
__global__ void gather_kernel(int l, const float* __restrict__ bias, float* __restrict__ out)
{
    const int warp = (blockIdx.x * blockDim.x + threadIdx.x) >> 5;
    const int lane = threadIdx.x & 31;
    if (warp >= N_NODES) return;

    const int s = g_off[l * (N_NODES + 1) + warp];
    const int e = g_off[l * (N_NODES + 1) + warp + 1];
    const int2* ep   = g_epack + (size_t)l * N_EDGES;
    const uint2* hw2 = (const uint2*)g_hwh;

    float4 a0 = make_float4(0.f, 0.f, 0.f, 0.f);
    float4 a1 = make_float4(0.f, 0.f, 0.f, 0.f);
    float4 a2 = make_float4(0.f, 0.f, 0.f, 0.f);
    float4 a3 = make_float4(0.f, 0.f, 0.f, 0.f);

    int p = s;
    for (; p + 4 <= e; p += 4) {
        int2 e0 = ep[p];
        int2 e1 = ep[p + 1];
        int2 e2 = ep[p + 2];
        int2 e3 = ep[p + 3];
        uint2 u0 = hw2[(size_t)e0.x * 32 + lane];
        uint2 u1 = hw2[(size_t)e1.x * 32 + lane];
        uint2 u2 = hw2[(size_t)e2.x * 32 + lane];
        uint2 u3 = hw2[(size_t)e3.x * 32 + lane];
        float n0 = __int_as_float(e0.y), n1 = __int_as_float(e1.y);
        float n2 = __int_as_float(e2.y), n3 = __int_as_float(e3.y);
        float2 f;
        f = __half22float2(*(__half2*)&u0.x); a0.x += n0 * f.x; a0.y += n0 * f.y;
        f = __half22float2(*(__half2*)&u0.y); a0.z += n0 * f.x; a0.w += n0 * f.y;
        f = __half22float2(*(__half2*)&u1.x); a1.x += n1 * f.x; a1.y += n1 * f.y;
        f = __half22float2(*(__half2*)&u1.y); a1.z += n1 * f.x; a1.w += n1 * f.y;
        f = __half22float2(*(__half2*)&u2.x); a2.x += n2 * f.x; a2.y += n2 * f.y;
        f = __half22float2(*(__half2*)&u2.y); a2.z += n2 * f.x; a2.w += n2 * f.y;
        f = __half22float2(*(__half2*)&u3.x); a3.x += n3 * f.x; a3.y += n3 * f.y;
        f = __half22float2(*(__half2*)&u3.y); a3.z += n3 * f.x; a3.w += n3 * f.y;
    }
    for (; p < e; p++) {
        int2 e0 = ep[p];
        float n0 = __int_as_float(e0.y);
        uint2 u0 = hw2[(size_t)e0.x * 32 + lane];
        float2 f;
        f = __half22float2(*(__half2*)&u0.x); a0.x += n0 * f.x; a0.y += n0 * f.y;
        f = __half22float2(*(__half2*)&u0.y); a0.z += n0 * f.x; a0.w += n0 * f.y;
    }

    float4 b = ((const float4*)bias)[lane];
    a0.x = fmaxf(a0.x + a1.x + a2.x + a3.x + b.x, 0.f);
    a0.y = fmaxf(a0.y + a1.y + a2.y + a3.y + b.y, 0.f);
    a0.z = fmaxf(a0.z + a1.z + a2.z + a3.z + b.z, 0.f);
    a0.w = fmaxf(a0.w + a1.w + a2.w + a3.w + b.w, 0.f);
    ((float4*)out)[(size_t)warp * 32 + lane] = a0;
}

// ---------------- launch ----------------------------------------------------
extern "C" void kernel_launch(void* const* d_in, const int* in_sizes, int n_in,
                              void* d_out, int out_size)
{
    const float* x      = (const float*)d_in[0];
    const int*   eidx   = (const int*)d_in[1];     // [ALPHA, 2, E] (int32 payload)
    const float* eattr  = (const float*)d_in[2];   // [ALPHA, E]
    const float* lin_w  = (const float*)d_in[3];
    const float* lin_b  = (const float*)d_in[4];
    const float* conv_w = (const float*)d_in[5];   // [ALPHA, D, D]
    const float* conv_b = (const float*)d_in[6];   // [ALPHA, D]
    float*       out    = (float*)d_out;           // [ALPHA+1, N, D]

    void* hw_ptr = nullptr;
    cudaGetSymbolAddress(&hw_ptr, g_hwh);

    const int smem_bytes = 2 * TILE_M * LDA * (int)sizeof(float);   // 135168
    cudaFuncSetAttribute(gemm_mma, cudaFuncAttributeMaxDynamicSharedMemorySize, smem_bytes);

    const int gemm_blocks      = (N_NODES + TILE_M - 1) / TILE_M;
    const int all_node_blocks  = (ALPHA * N_NODES + 255) / 256;
    const int edge_blocks      = (N_EDGES + 255) / 256;
    const int gather_blocks    = (N_NODES * 32 + 255) / 256;

    // fork: prep chain on side stream, GEMMs on main stream (capture-legal)
    cudaStream_t sp;
    cudaStreamCreateWithFlags(&sp, cudaStreamNonBlocking);
    cudaEvent_t ev_fork, ev_join;
    cudaEventCreateWithFlags(&ev_fork, cudaEventDisableTiming);
    cudaEventCreateWithFlags(&ev_join, cudaEventDisableTiming);

    cudaEventRecord(ev_fork, 0);
    cudaStreamWaitEvent(sp, ev_fork, 0);

    clear_kernel<<<all_node_blocks, 256, 0, sp>>>();
    deg_kernel<<<dim3(edge_blocks, ALPHA), 256, 0, sp>>>(eidx, eattr);
    dinv_kernel<<<all_node_blocks, 256, 0, sp>>>();
    scan_p1<<<dim3(NB, ALPHA), SCAN_BLK, 0, sp>>>();
    scan_p2<<<1, 128, 0, sp>>>();
    scan_p3<<<dim3(NB, ALPHA), SCAN_BLK, 0, sp>>>();
    bin_kernel<<<dim3(edge_blocks, ALPHA), 256, 0, sp>>>(eidx, eattr);
    cudaEventRecord(ev_join, sp);

    // main stream: h0 = relu(x @ lin_w.T + lin_b) and hw0 overlap with prep
    gemm_mma<<<gemm_blocks, GT, smem_bytes>>>(x, lin_w, lin_b, out, N_NODES, 1, 0);
    gemm_mma<<<gemm_blocks, GT, smem_bytes>>>(out, conv_w, nullptr, hw_ptr, N_NODES, 0, 1);

    // join: gathers need the CSR from the prep chain
    cudaStreamWaitEvent(0, ev_join, 0);

    for (int i = 0; i < ALPHA; i++) {
        const float* b    = conv_b + (size_t)i * DIM;
        float*       hout = out + (size_t)(i + 1) * N_NODES * DIM;

        gather_kernel<<<gather_blocks, 256>>>(i, b, hout);

        if (i + 1 < ALPHA) {
            const float* Wn = conv_w + (size_t)(i + 1) * DIM * DIM;
            gemm_mma<<<gemm_blocks, GT, smem_bytes>>>(hout, Wn, nullptr, hw_ptr, N_NODES, 0, 1);
        }
    }
}

// round 14
// speedup vs baseline: 1.0717x; 1.0717x over previous
#include <cuda_runtime.h>
#include <cuda_fp16.h>
#include <cstdint>

#define N_NODES 100000
#define N_EDGES 1600000
#define DIM     128
#define ALPHA   4

#define SCAN_BLK   1024
#define SCAN_ELEMS 2048
#define NB ((N_NODES + SCAN_ELEMS - 1) / SCAN_ELEMS)   // 49

// ---------------- scratch (device globals; no allocations allowed) ----------
__device__ __half             g_hwh[(size_t)N_NODES * DIM];   // h @ W.T (fp16)
__device__ unsigned long long g_degpack[ALPHA * N_NODES];     // count<<40 | fx24 deg
__device__ float              g_dinv[ALPHA * N_NODES];
__device__ int                g_cnt[ALPHA * N_NODES];
__device__ int                g_off[ALPHA * (N_NODES + 1)];
__device__ int                g_cursor[ALPHA * N_NODES];
__device__ int                g_bsum[ALPHA * NB];
__device__ int2               g_epack[(size_t)ALPHA * N_EDGES];  // {src row, norm bits}

// ============================================================================
// TF32 3-pass GEMM via mma.sync. out[r][n] = act(sum_k in[r][k]*W[n][k] (+b))
// out_half=0: write fp32 to out. out_half=1: write fp16 to (half*)out.
// ============================================================================
#define TILE_M   128
#define GT       256
#define LDA      132

__device__ __forceinline__ uint32_t f2tf32(float x) {
    uint32_t r;
    asm("cvt.rna.tf32.f32 %0, %1;" : "=r"(r) : "f"(x));
    return r;
}

__device__ __forceinline__ void mma_tf32(float c[4],
                                         uint32_t a0, uint32_t a1, uint32_t a2, uint32_t a3,
                                         uint32_t b0, uint32_t b1) {
    asm volatile(
        "mma.sync.aligned.m16n8k8.row.col.f32.tf32.tf32.f32 "
        "{%0,%1,%2,%3}, {%4,%5,%6,%7}, {%8,%9}, {%0,%1,%2,%3};"
        : "+f"(c[0]), "+f"(c[1]), "+f"(c[2]), "+f"(c[3])
        : "r"(a0), "r"(a1), "r"(a2), "r"(a3), "r"(b0), "r"(b1));
}

__global__ void __launch_bounds__(GT, 1)
gemm_mma(const float* __restrict__ in, const float* __restrict__ W,
         const float* __restrict__ bias, void* __restrict__ out,
         int n_rows, int do_relu, int out_half)
{
    extern __shared__ float smem[];
    float* As = smem;
    float* Ws = smem + TILE_M * LDA;

    const int tid  = threadIdx.x;
    const int wid  = tid >> 5;
    const int lane = tid & 31;
    const int gid  = lane >> 2;
    const int tig  = lane & 3;
    const int wm   = wid & 3;
    const int wn   = wid >> 2;
    const int row0 = blockIdx.x * TILE_M;

    const float4* in4 = (const float4*)in;
    #pragma unroll
    for (int i = 0; i < (TILE_M * 32) / GT; i++) {
        int idx = tid + i * GT;
        int r   = idx >> 5;
        int c4  = idx & 31;
        int row = row0 + r;
        float4 v = make_float4(0.f, 0.f, 0.f, 0.f);
        if (row < n_rows) v = in4[(size_t)row * 32 + c4];
        *(float4*)&As[r * LDA + c4 * 4] = v;
    }
    const float4* W4 = (const float4*)W;
    #pragma unroll
    for (int i = 0; i < (DIM * 32) / GT; i++) {
        int idx = tid + i * GT;
        int r   = idx >> 5;
        int c4  = idx & 31;
        *(float4*)&Ws[r * LDA + c4 * 4] = W4[(size_t)r * 32 + c4];
    }
    __syncthreads();

    float c[2][8][4];
    #pragma unroll
    for (int mi = 0; mi < 2; mi++)
        #pragma unroll
        for (int ni = 0; ni < 8; ni++)
            #pragma unroll
            for (int j = 0; j < 4; j++)
                c[mi][ni][j] = 0.f;

    #pragma unroll
    for (int ks = 0; ks < DIM / 8; ks++) {
        const int k0 = ks * 8;

        uint32_t ah[2][4], al[2][4];
        #pragma unroll
        for (int mi = 0; mi < 2; mi++) {
            const int rb = wm * 32 + mi * 16;
            float v0 = As[(rb + gid)     * LDA + k0 + tig];
            float v1 = As[(rb + gid + 8) * LDA + k0 + tig];
            float v2 = As[(rb + gid)     * LDA + k0 + tig + 4];
            float v3 = As[(rb + gid + 8) * LDA + k0 + tig + 4];
            ah[mi][0] = f2tf32(v0); al[mi][0] = f2tf32(v0 - __uint_as_float(ah[mi][0]));
            ah[mi][1] = f2tf32(v1); al[mi][1] = f2tf32(v1 - __uint_as_float(ah[mi][1]));
            ah[mi][2] = f2tf32(v2); al[mi][2] = f2tf32(v2 - __uint_as_float(ah[mi][2]));
            ah[mi][3] = f2tf32(v3); al[mi][3] = f2tf32(v3 - __uint_as_float(ah[mi][3]));
        }
        uint32_t bh[8][2], bl[8][2];
        #pragma unroll
        for (int ni = 0; ni < 8; ni++) {
            const int col = wn * 64 + ni * 8 + gid;
            float v0 = Ws[col * LDA + k0 + tig];
            float v1 = Ws[col * LDA + k0 + tig + 4];
            bh[ni][0] = f2tf32(v0); bl[ni][0] = f2tf32(v0 - __uint_as_float(bh[ni][0]));
            bh[ni][1] = f2tf32(v1); bl[ni][1] = f2tf32(v1 - __uint_as_float(bh[ni][1]));
        }

        #pragma unroll
        for (int mi = 0; mi < 2; mi++)
            #pragma unroll
            for (int ni = 0; ni < 8; ni++) {
                mma_tf32(c[mi][ni], ah[mi][0], ah[mi][1], ah[mi][2], ah[mi][3],
                         bh[ni][0], bh[ni][1]);
                mma_tf32(c[mi][ni], al[mi][0], al[mi][1], al[mi][2], al[mi][3],
                         bh[ni][0], bh[ni][1]);
                mma_tf32(c[mi][ni], ah[mi][0], ah[mi][1], ah[mi][2], ah[mi][3],
                         bl[ni][0], bl[ni][1]);
            }
    }
    __syncthreads();

    float* stage = As;
    #pragma unroll
    for (int mi = 0; mi < 2; mi++) {
        const int rb = wm * 32 + mi * 16;
        #pragma unroll
        for (int ni = 0; ni < 8; ni++) {
            const int cb = wn * 64 + ni * 8 + tig * 2;
            *(float2*)&stage[(rb + gid)     * LDA + cb] = make_float2(c[mi][ni][0], c[mi][ni][1]);
            *(float2*)&stage[(rb + gid + 8) * LDA + cb] = make_float2(c[mi][ni][2], c[mi][ni][3]);
        }
    }
    __syncthreads();

    #pragma unroll
    for (int i = 0; i < (TILE_M * 32) / GT; i++) {
        int idx = tid + i * GT;
        int r   = idx >> 5;
        int c4  = idx & 31;
        int row = row0 + r;
        if (row < n_rows) {
            float4 v = *(float4*)&stage[r * LDA + c4 * 4];
            if (bias) {
                const float4 b = *(const float4*)&bias[c4 * 4];
                v.x += b.x; v.y += b.y; v.z += b.z; v.w += b.w;
            }
            if (do_relu) {
                v.x = fmaxf(v.x, 0.f); v.y = fmaxf(v.y, 0.f);
                v.z = fmaxf(v.z, 0.f); v.w = fmaxf(v.w, 0.f);
            }
            if (out_half) {
                __half2 h0 = __floats2half2_rn(v.x, v.y);
                __half2 h1 = __floats2half2_rn(v.z, v.w);
                uint2 u = make_uint2(*(uint32_t*)&h0, *(uint32_t*)&h1);
                ((uint2*)out)[(size_t)row * 32 + c4] = u;
            } else {
                ((float4*)out)[(size_t)row * 32 + c4] = v;
            }
        }
    }
}

// ============================================================================
// batched per-layer graph prep (all ALPHA layers at once)
// ============================================================================
__global__ void clear_kernel()
{
    int i = blockIdx.x * blockDim.x + threadIdx.x;
    if (i < ALPHA * N_NODES) g_degpack[i] = 0ULL;
}

__global__ void deg_kernel(const int* __restrict__ eidx, const float* __restrict__ eattr)
{
    int e = blockIdx.x * blockDim.x + threadIdx.x;
    int l = blockIdx.y;
    if (e >= N_EDGES) return;
    int   c = eidx[(size_t)l * 2 * N_EDGES + N_EDGES + e];
    float a = eattr[(size_t)l * N_EDGES + e];
    unsigned long long add =
        (1ULL << 40) | (unsigned long long)(unsigned int)__float2uint_rn(a * 16777216.f);
    atomicAdd(&g_degpack[l * N_NODES + c], add);
}

__global__ void dinv_kernel()
{
    int i = blockIdx.x * blockDim.x + threadIdx.x;
    if (i < ALPHA * N_NODES) {
        unsigned long long v = g_degpack[i];
        int   cnt = (int)(v >> 40);
        float d   = (float)(v & 0xFFFFFFFFFFULL) * (1.f / 16777216.f);
        g_cnt[i]  = cnt;
        g_dinv[i] = (d > 0.f) ? rsqrtf(d) : 0.f;
    }
}

__global__ void scan_p1()
{
    const int l = blockIdx.y, b = blockIdx.x, tid = threadIdx.x;
    const int i0 = b * SCAN_ELEMS + tid * 2;
    int s = 0;
    if (i0     < N_NODES) s += g_cnt[l * N_NODES + i0];
    if (i0 + 1 < N_NODES) s += g_cnt[l * N_NODES + i0 + 1];

    __shared__ int sh[SCAN_BLK];
    sh[tid] = s;
    __syncthreads();
    #pragma unroll
    for (int ofs = SCAN_BLK / 2; ofs > 0; ofs >>= 1) {
        if (tid < ofs) sh[tid] += sh[tid + ofs];
        __syncthreads();
    }
    if (tid == 0) g_bsum[l * NB + b] = sh[0];
}

__global__ void scan_p2()
{
    int l = threadIdx.x;
    if (l < ALPHA) {
        int run = 0;
        for (int b = 0; b < NB; b++) {
            int v = g_bsum[l * NB + b];
            g_bsum[l * NB + b] = run;
            run += v;
        }
    }
}

__global__ void scan_p3()
{
    const int l = blockIdx.y, b = blockIdx.x, tid = threadIdx.x;
    const int i0 = b * SCAN_ELEMS + tid * 2;
    int v0 = 0, v1 = 0;
    if (i0     < N_NODES) v0 = g_cnt[l * N_NODES + i0];
    if (i0 + 1 < N_NODES) v1 = g_cnt[l * N_NODES + i0 + 1];
    const int tsum = v0 + v1;

    __shared__ int sh[SCAN_BLK];
    sh[tid] = tsum;
    __syncthreads();
    #pragma unroll
    for (int ofs = 1; ofs < SCAN_BLK; ofs <<= 1) {
        int x = (tid >= ofs) ? sh[tid - ofs] : 0;
        __syncthreads();
        sh[tid] += x;
        __syncthreads();
    }
    const int texcl = sh[tid] - tsum + g_bsum[l * NB + b];
    if (i0 < N_NODES) {
        g_off[l * (N_NODES + 1) + i0] = texcl;
        g_cursor[l * N_NODES + i0]    = texcl;
    }
    if (i0 + 1 < N_NODES) {
        g_off[l * (N_NODES + 1) + i0 + 1] = texcl + v0;
        g_cursor[l * N_NODES + i0 + 1]    = texcl + v0;
    }
    if (b == NB - 1 && tid == SCAN_BLK - 1)
        g_off[l * (N_NODES + 1) + N_NODES] = texcl + tsum;
}

__global__ void bin_kernel(const int* __restrict__ eidx, const float* __restrict__ eattr)
{
    int e = blockIdx.x * blockDim.x + threadIdx.x;
    int l = blockIdx.y;
    if (e >= N_EDGES) return;
    int r = eidx[(size_t)l * 2 * N_EDGES + e];
    int c = eidx[(size_t)l * 2 * N_EDGES + N_EDGES + e];
    int p = atomicAdd(&g_cursor[l * N_NODES + c], 1);
    float norm = g_dinv[l * N_NODES + r] * eattr[(size_t)l * N_EDGES + e]
               * g_dinv[l * N_NODES + c];
    g_epack[(size_t)l * N_EDGES + p] = make_int2(r, __float_as_int(norm));
}

// one warp per destination node; fp16 rows (256B), x2 unroll, fp32 accum
__global__ void gather_kernel(int l, const float* __restrict__ bias, float* __restrict__ out)
{
    const int warp = (blockIdx.x * blockDim.x + threadIdx.x) >> 5;
    const int lane = threadIdx.x & 31;
    if (warp >= N_NODES) return;

    const int s = g_off[l * (N_NODES + 1) + warp];
    const int e = g_off[l * (N_NODES + 1) + warp + 1];
    const int2* ep   = g_epack + (size_t)l * N_EDGES;
    const uint2* hw2 = (const uint2*)g_hwh;

    float4 acc0 = make_float4(0.f, 0.f, 0.f, 0.f);
    float4 acc1 = make_float4(0.f, 0.f, 0.f, 0.f);

    int p = s;
    for (; p + 2 <= e; p += 2) {
        int2 e0 = ep[p];
        int2 e1 = ep[p + 1];
        float n0 = __int_as_float(e0.y);
        float n1 = __int_as_float(e1.y);
        uint2 u0 = hw2[(size_t)e0.x * 32 + lane];
        uint2 u1 = hw2[(size_t)e1.x * 32 + lane];
        float2 f0a = __half22float2(*(__half2*)&u0.x);
        float2 f0b = __half22float2(*(__half2*)&u0.y);
        float2 f1a = __half22float2(*(__half2*)&u1.x);
        float2 f1b = __half22float2(*(__half2*)&u1.y);
        acc0.x += n0 * f0a.x; acc0.y += n0 * f0a.y; acc0.z += n0 * f0b.x; acc0.w += n0 * f0b.y;
        acc1.x += n1 * f1a.x; acc1.y += n1 * f1a.y; acc1.z += n1 * f1b.x; acc1.w += n1 * f1b.y;
    }
    if (p < e) {
        int2 e0 = ep[p];
        float n0 = __int_as_float(e0.y);
        uint2 u0 = hw2[(size_t)e0.x * 32 + lane];
        float2 f0a = __half22float2(*(__half2*)&u0.x);
        float2 f0b = __half22float2(*(__half2*)&u0.y);
        acc0.x += n0 * f0a.x; acc0.y += n0 * f0a.y; acc0.z += n0 * f0b.x; acc0.w += n0 * f0b.y;
    }

    float4 b = ((const float4*)bias)[lane];
    acc0.x = fmaxf(acc0.x + acc1.x + b.x, 0.f);
    acc0.y = fmaxf(acc0.y + acc1.y + b.y, 0.f);
    acc0.z = fmaxf(acc0.z + acc1.z + b.z, 0.f);
    acc0.w = fmaxf(acc0.w + acc1.w + b.w, 0.f);
    ((float4*)out)[(size_t)warp * 32 + lane] = acc0;
}

// ---------------- launch ----------------------------------------------------
extern "C" void kernel_launch(void* const* d_in, const int* in_sizes, int n_in,
                              void* d_out, int out_size)
{
    const float* x      = (const float*)d_in[0];
    const int*   eidx   = (const int*)d_in[1];     // [ALPHA, 2, E] (int32 payload)
    const float* eattr  = (const float*)d_in[2];   // [ALPHA, E]
    const float* lin_w  = (const float*)d_in[3];
    const float* lin_b  = (const float*)d_in[4];
    const float* conv_w = (const float*)d_in[5];   // [ALPHA, D, D]
    const float* conv_b = (const float*)d_in[6];   // [ALPHA, D]
    float*       out    = (float*)d_out;           // [ALPHA+1, N, D]

    void* hw_ptr = nullptr;
    cudaGetSymbolAddress(&hw_ptr, g_hwh);

    const int smem_bytes = 2 * TILE_M * LDA * (int)sizeof(float);   // 135168
    cudaFuncSetAttribute(gemm_mma, cudaFuncAttributeMaxDynamicSharedMemorySize, smem_bytes);

    const int gemm_blocks      = (N_NODES + TILE_M - 1) / TILE_M;
    const int all_node_blocks  = (ALPHA * N_NODES + 255) / 256;
    const int edge_blocks      = (N_EDGES + 255) / 256;
    const int gather_blocks    = (N_NODES * 32 + 255) / 256;

    // fork: prep chain on side stream, first GEMMs on main stream
    static cudaStream_t sp = nullptr;
    static cudaEvent_t ev_fork = nullptr, ev_join = nullptr;
    if (!sp) {
        cudaStreamCreateWithFlags(&sp, cudaStreamNonBlocking);
        cudaEventCreateWithFlags(&ev_fork, cudaEventDisableTiming);
        cudaEventCreateWithFlags(&ev_join, cudaEventDisableTiming);
    }

    cudaEventRecord(ev_fork, 0);
    cudaStreamWaitEvent(sp, ev_fork, 0);

    clear_kernel<<<all_node_blocks, 256, 0, sp>>>();
    deg_kernel<<<dim3(edge_blocks, ALPHA), 256, 0, sp>>>(eidx, eattr);
    dinv_kernel<<<all_node_blocks, 256, 0, sp>>>();
    scan_p1<<<dim3(NB, ALPHA), SCAN_BLK, 0, sp>>>();
    scan_p2<<<1, 128, 0, sp>>>();
    scan_p3<<<dim3(NB, ALPHA), SCAN_BLK, 0, sp>>>();
    bin_kernel<<<dim3(edge_blocks, ALPHA), 256, 0, sp>>>(eidx, eattr);
    cudaEventRecord(ev_join, sp);

    // main stream: h0 = relu(x @ lin_w.T + lin_b), hw0 — overlap with prep
    gemm_mma<<<gemm_blocks, GT, smem_bytes>>>(x, lin_w, lin_b, out, N_NODES, 1, 0);
    gemm_mma<<<gemm_blocks, GT, smem_bytes>>>(out, conv_w, nullptr, hw_ptr, N_NODES, 0, 1);

    // join: gathers need the CSR from the prep chain
    cudaStreamWaitEvent(0, ev_join, 0);

    for (int i = 0; i < ALPHA; i++) {
        const float* b    = conv_b + (size_t)i * DIM;
        float*       hout = out + (size_t)(i + 1) * N_NODES * DIM;

        gather_kernel<<<gather_blocks, 256>>>(i, b, hout);

        if (i + 1 < ALPHA) {
            const float* Wn = conv_w + (size_t)(i + 1) * DIM * DIM;
            gemm_mma<<<gemm_blocks, GT, smem_bytes>>>(hout, Wn, nullptr, hw_ptr, N_NODES, 0, 1);
        }
    }
}

// round 16
// speedup vs baseline: 1.4604x; 1.3627x over previous
#include <cuda_runtime.h>
#include <cuda_fp16.h>
#include <cstdint>

#define N_NODES 100000
#define N_EDGES 1600000
#define DIM     128
#define ALPHA   4

#define SCAN_BLK   1024
#define SCAN_ELEMS 2048
#define NB ((N_NODES + SCAN_ELEMS - 1) / SCAN_ELEMS)   // 49

// ---------------- scratch (device globals; no allocations allowed) ----------
__device__ __half             g_hwh[(size_t)N_NODES * DIM];   // h @ W.T (fp16)
__device__ unsigned long long g_degpack[ALPHA * N_NODES];     // count<<40 | fx24 deg
__device__ float              g_dinv[ALPHA * N_NODES];
__device__ int                g_cnt[ALPHA * N_NODES];
__device__ int                g_off[ALPHA * (N_NODES + 1)];
__device__ int                g_cursor[ALPHA * N_NODES];
__device__ int                g_bsum[ALPHA * NB];
__device__ int2               g_epack[(size_t)ALPHA * N_EDGES];  // {src row, norm bits}

// ============================================================================
// FP16 3-pass GEMM via mma.sync.m16n8k16 (error-compensated: hh + hl + lh).
// out[r][n] = act(sum_k in[r][k]*W[n][k] (+b)); hi/lo split once at load.
// ============================================================================
#define TILE_M   128
#define GT       256
#define LDA      132          // fp32 stage lead dim
#define LDAH     136          // fp16 tile lead dim (halfs): bank-perm (4*gid+tig)

__device__ __forceinline__ void mma_f16(float c[4],
                                        uint32_t a0, uint32_t a1, uint32_t a2, uint32_t a3,
                                        uint32_t b0, uint32_t b1) {
    asm volatile(
        "mma.sync.aligned.m16n8k16.row.col.f32.f16.f16.f32 "
        "{%0,%1,%2,%3}, {%4,%5,%6,%7}, {%8,%9}, {%0,%1,%2,%3};"
        : "+f"(c[0]), "+f"(c[1]), "+f"(c[2]), "+f"(c[3])
        : "r"(a0), "r"(a1), "r"(a2), "r"(a3), "r"(b0), "r"(b1));
}

__device__ __forceinline__ void split2(float x, float y, uint32_t& hi, uint32_t& lo) {
    __half h0 = __float2half_rn(x);
    __half h1 = __float2half_rn(y);
    __half l0 = __float2half_rn(x - __half2float(h0));
    __half l1 = __float2half_rn(y - __half2float(h1));
    __half2 hp = __halves2half2(h0, h1);
    __half2 lp = __halves2half2(l0, l1);
    hi = *(uint32_t*)&hp;
    lo = *(uint32_t*)&lp;
}

__global__ void __launch_bounds__(GT, 1)
gemm_mma(const float* __restrict__ in, const float* __restrict__ W,
         const float* __restrict__ bias, void* __restrict__ out,
         int n_rows, int do_relu, int out_half)
{
    extern __shared__ char smem[];
    __half* Ah = (__half*)smem;                       // [128][LDAH]
    __half* Al = Ah + TILE_M * LDAH;
    __half* Wh = Al + TILE_M * LDAH;
    __half* Wl = Wh + DIM * LDAH;

    const int tid  = threadIdx.x;
    const int wid  = tid >> 5;
    const int lane = tid & 31;
    const int gid  = lane >> 2;
    const int tig  = lane & 3;
    const int wm   = wid & 3;
    const int wn   = wid >> 2;
    const int row0 = blockIdx.x * TILE_M;

    // ---- load A tile, split hi/lo once (fp16 planes) ----
    const float4* in4 = (const float4*)in;
    #pragma unroll
    for (int i = 0; i < (TILE_M * 32) / GT; i++) {
        int idx = tid + i * GT;
        int r   = idx >> 5;
        int c4  = idx & 31;
        int row = row0 + r;
        float4 v = make_float4(0.f, 0.f, 0.f, 0.f);
        if (row < n_rows) v = in4[(size_t)row * 32 + c4];
        uint2 hi, lo;
        split2(v.x, v.y, hi.x, lo.x);
        split2(v.z, v.w, hi.y, lo.y);
        *(uint2*)&Ah[r * LDAH + c4 * 4] = hi;
        *(uint2*)&Al[r * LDAH + c4 * 4] = lo;
    }
    // ---- load W tile, split hi/lo once ----
    const float4* W4 = (const float4*)W;
    #pragma unroll
    for (int i = 0; i < (DIM * 32) / GT; i++) {
        int idx = tid + i * GT;
        int r   = idx >> 5;
        int c4  = idx & 31;
        float4 v = W4[(size_t)r * 32 + c4];
        uint2 hi, lo;
        split2(v.x, v.y, hi.x, lo.x);
        split2(v.z, v.w, hi.y, lo.y);
        *(uint2*)&Wh[r * LDAH + c4 * 4] = hi;
        *(uint2*)&Wl[r * LDAH + c4 * 4] = lo;
    }
    __syncthreads();

    float c[2][8][4];
    #pragma unroll
    for (int mi = 0; mi < 2; mi++)
        #pragma unroll
        for (int ni = 0; ni < 8; ni++)
            #pragma unroll
            for (int j = 0; j < 4; j++)
                c[mi][ni][j] = 0.f;

    #pragma unroll
    for (int ks = 0; ks < DIM / 16; ks++) {
        const int k0 = ks * 16;
        const int kA = k0 + tig * 2;       // this thread's k pair

        // A fragments (m16n8k16): 4 regs per mi tile, hi and lo planes
        uint32_t ah[2][4], al[2][4];
        #pragma unroll
        for (int mi = 0; mi < 2; mi++) {
            const int rb = wm * 32 + mi * 16;
            ah[mi][0] = *(uint32_t*)&Ah[(rb + gid)     * LDAH + kA];
            ah[mi][1] = *(uint32_t*)&Ah[(rb + gid + 8) * LDAH + kA];
            ah[mi][2] = *(uint32_t*)&Ah[(rb + gid)     * LDAH + kA + 8];
            ah[mi][3] = *(uint32_t*)&Ah[(rb + gid + 8) * LDAH + kA + 8];
            al[mi][0] = *(uint32_t*)&Al[(rb + gid)     * LDAH + kA];
            al[mi][1] = *(uint32_t*)&Al[(rb + gid + 8) * LDAH + kA];
            al[mi][2] = *(uint32_t*)&Al[(rb + gid)     * LDAH + kA + 8];
            al[mi][3] = *(uint32_t*)&Al[(rb + gid + 8) * LDAH + kA + 8];
        }
        // B fragments: 2 regs per ni tile (col-major k,n), hi and lo
        uint32_t bh[8][2], bl[8][2];
        #pragma unroll
        for (int ni = 0; ni < 8; ni++) {
            const int col = wn * 64 + ni * 8 + gid;
            bh[ni][0] = *(uint32_t*)&Wh[col * LDAH + kA];
            bh[ni][1] = *(uint32_t*)&Wh[col * LDAH + kA + 8];
            bl[ni][0] = *(uint32_t*)&Wl[col * LDAH + kA];
            bl[ni][1] = *(uint32_t*)&Wl[col * LDAH + kA + 8];
        }

        #pragma unroll
        for (int mi = 0; mi < 2; mi++)
            #pragma unroll
            for (int ni = 0; ni < 8; ni++) {
                mma_f16(c[mi][ni], ah[mi][0], ah[mi][1], ah[mi][2], ah[mi][3],
                        bh[ni][0], bh[ni][1]);
                mma_f16(c[mi][ni], al[mi][0], al[mi][1], al[mi][2], al[mi][3],
                        bh[ni][0], bh[ni][1]);
                mma_f16(c[mi][ni], ah[mi][0], ah[mi][1], ah[mi][2], ah[mi][3],
                        bl[ni][0], bl[ni][1]);
            }
    }
    __syncthreads();

    // ---- epilogue: frags -> fp32 smem stage (reuse tile region) -> out ----
    float* stage = (float*)smem;   // [128][LDA]; fits within Ah+Al planes
    #pragma unroll
    for (int mi = 0; mi < 2; mi++) {
        const int rb = wm * 32 + mi * 16;
        #pragma unroll
        for (int ni = 0; ni < 8; ni++) {
            const int cb = wn * 64 + ni * 8 + tig * 2;
            *(float2*)&stage[(rb + gid)     * LDA + cb] = make_float2(c[mi][ni][0], c[mi][ni][1]);
            *(float2*)&stage[(rb + gid + 8) * LDA + cb] = make_float2(c[mi][ni][2], c[mi][ni][3]);
        }
    }
    __syncthreads();

    #pragma unroll
    for (int i = 0; i < (TILE_M * 32) / GT; i++) {
        int idx = tid + i * GT;
        int r   = idx >> 5;
        int c4  = idx & 31;
        int row = row0 + r;
        if (row < n_rows) {
            float4 v = *(float4*)&stage[r * LDA + c4 * 4];
            if (bias) {
                const float4 b = *(const float4*)&bias[c4 * 4];
                v.x += b.x; v.y += b.y; v.z += b.z; v.w += b.w;
            }
            if (do_relu) {
                v.x = fmaxf(v.x, 0.f); v.y = fmaxf(v.y, 0.f);
                v.z = fmaxf(v.z, 0.f); v.w = fmaxf(v.w, 0.f);
            }
            if (out_half) {
                __half2 h0 = __floats2half2_rn(v.x, v.y);
                __half2 h1 = __floats2half2_rn(v.z, v.w);
                uint2 u = make_uint2(*(uint32_t*)&h0, *(uint32_t*)&h1);
                ((uint2*)out)[(size_t)row * 32 + c4] = u;
            } else {
                ((float4*)out)[(size_t)row * 32 + c4] = v;
            }
        }
    }
}

// ============================================================================
// batched per-layer graph prep (all ALPHA layers at once)
// ============================================================================
__global__ void clear_kernel()
{
    int i = blockIdx.x * blockDim.x + threadIdx.x;
    if (i < ALPHA * N_NODES) g_degpack[i] = 0ULL;
}

__global__ void deg_kernel(const int* __restrict__ eidx, const float* __restrict__ eattr)
{
    int e = blockIdx.x * blockDim.x + threadIdx.x;
    int l = blockIdx.y;
    if (e >= N_EDGES) return;
    int   c = eidx[(size_t)l * 2 * N_EDGES + N_EDGES + e];
    float a = eattr[(size_t)l * N_EDGES + e];
    unsigned long long add =
        (1ULL << 40) | (unsigned long long)(unsigned int)__float2uint_rn(a * 16777216.f);
    atomicAdd(&g_degpack[l * N_NODES + c], add);
}

__global__ void dinv_kernel()
{
    int i = blockIdx.x * blockDim.x + threadIdx.x;
    if (i < ALPHA * N_NODES) {
        unsigned long long v = g_degpack[i];
        int   cnt = (int)(v >> 40);
        float d   = (float)(v & 0xFFFFFFFFFFULL) * (1.f / 16777216.f);
        g_cnt[i]  = cnt;
        g_dinv[i] = (d > 0.f) ? rsqrtf(d) : 0.f;
    }
}

__global__ void scan_p1()
{
    const int l = blockIdx.y, b = blockIdx.x, tid = threadIdx.x;
    const int i0 = b * SCAN_ELEMS + tid * 2;
    int s = 0;
    if (i0     < N_NODES) s += g_cnt[l * N_NODES + i0];
    if (i0 + 1 < N_NODES) s += g_cnt[l * N_NODES + i0 + 1];

    __shared__ int sh[SCAN_BLK];
    sh[tid] = s;
    __syncthreads();
    #pragma unroll
    for (int ofs = SCAN_BLK / 2; ofs > 0; ofs >>= 1) {
        if (tid < ofs) sh[tid] += sh[tid + ofs];
        __syncthreads();
    }
    if (tid == 0) g_bsum[l * NB + b] = sh[0];
}

__global__ void scan_p2()
{
    int l = threadIdx.x;
    if (l < ALPHA) {
        int run = 0;
        for (int b = 0; b < NB; b++) {
            int v = g_bsum[l * NB + b];
            g_bsum[l * NB + b] = run;
            run += v;
        }
    }
}

__global__ void scan_p3()
{
    const int l = blockIdx.y, b = blockIdx.x, tid = threadIdx.x;
    const int i0 = b * SCAN_ELEMS + tid * 2;
    int v0 = 0, v1 = 0;
    if (i0     < N_NODES) v0 = g_cnt[l * N_NODES + i0];
    if (i0 + 1 < N_NODES) v1 = g_cnt[l * N_NODES + i0 + 1];
    const int tsum = v0 + v1;

    __shared__ int sh[SCAN_BLK];
    sh[tid] = tsum;
    __syncthreads();
    #pragma unroll
    for (int ofs = 1; ofs < SCAN_BLK; ofs <<= 1) {
        int x = (tid >= ofs) ? sh[tid - ofs] : 0;
        __syncthreads();
        sh[tid] += x;
        __syncthreads();
    }
    const int texcl = sh[tid] - tsum + g_bsum[l * NB + b];
    if (i0 < N_NODES) {
        g_off[l * (N_NODES + 1) + i0] = texcl;
        g_cursor[l * N_NODES + i0]    = texcl;
    }
    if (i0 + 1 < N_NODES) {
        g_off[l * (N_NODES + 1) + i0 + 1] = texcl + v0;
        g_cursor[l * N_NODES + i0 + 1]    = texcl + v0;
    }
    if (b == NB - 1 && tid == SCAN_BLK - 1)
        g_off[l * (N_NODES + 1) + N_NODES] = texcl + tsum;
}

__global__ void bin_kernel(const int* __restrict__ eidx, const float* __restrict__ eattr)
{
    int e = blockIdx.x * blockDim.x + threadIdx.x;
    int l = blockIdx.y;
    if (e >= N_EDGES) return;
    int r = eidx[(size_t)l * 2 * N_EDGES + e];
    int c = eidx[(size_t)l * 2 * N_EDGES + N_EDGES + e];
    int p = atomicAdd(&g_cursor[l * N_NODES + c], 1);
    float norm = g_dinv[l * N_NODES + r] * eattr[(size_t)l * N_EDGES + e]
               * g_dinv[l * N_NODES + c];
    g_epack[(size_t)l * N_EDGES + p] = make_int2(r, __float_as_int(norm));
}

// one warp per destination node; fp16 rows (256B), x2 unroll, fp32 accum
__global__ void gather_kernel(int l, const float* __restrict__ bias, float* __restrict__ out)
{
    const int warp = (blockIdx.x * blockDim.x + threadIdx.x) >> 5;
    const int lane = threadIdx.x & 31;
    if (warp >= N_NODES) return;

    const int s = g_off[l * (N_NODES + 1) + warp];
    const int e = g_off[l * (N_NODES + 1) + warp + 1];
    const int2* ep   = g_epack + (size_t)l * N_EDGES;
    const uint2* hw2 = (const uint2*)g_hwh;

    float4 acc0 = make_float4(0.f, 0.f, 0.f, 0.f);
    float4 acc1 = make_float4(0.f, 0.f, 0.f, 0.f);

    int p = s;
    for (; p + 2 <= e; p += 2) {
        int2 e0 = ep[p];
        int2 e1 = ep[p + 1];
        float n0 = __int_as_float(e0.y);
        float n1 = __int_as_float(e1.y);
        uint2 u0 = hw2[(size_t)e0.x * 32 + lane];
        uint2 u1 = hw2[(size_t)e1.x * 32 + lane];
        float2 f0a = __half22float2(*(__half2*)&u0.x);
        float2 f0b = __half22float2(*(__half2*)&u0.y);
        float2 f1a = __half22float2(*(__half2*)&u1.x);
        float2 f1b = __half22float2(*(__half2*)&u1.y);
        acc0.x += n0 * f0a.x; acc0.y += n0 * f0a.y; acc0.z += n0 * f0b.x; acc0.w += n0 * f0b.y;
        acc1.x += n1 * f1a.x; acc1.y += n1 * f1a.y; acc1.z += n1 * f1b.x; acc1.w += n1 * f1b.y;
    }
    if (p < e) {
        int2 e0 = ep[p];
        float n0 = __int_as_float(e0.y);
        uint2 u0 = hw2[(size_t)e0.x * 32 + lane];
        float2 f0a = __half22float2(*(__half2*)&u0.x);
        float2 f0b = __half22float2(*(__half2*)&u0.y);
        acc0.x += n0 * f0a.x; acc0.y += n0 * f0a.y; acc0.z += n0 * f0b.x; acc0.w += n0 * f0b.y;
    }

    float4 b = ((const float4*)bias)[lane];
    acc0.x = fmaxf(acc0.x + acc1.x + b.x, 0.f);
    acc0.y = fmaxf(acc0.y + acc1.y + b.y, 0.f);
    acc0.z = fmaxf(acc0.z + acc1.z + b.z, 0.f);
    acc0.w = fmaxf(acc0.w + acc1.w + b.w, 0.f);
    ((float4*)out)[(size_t)warp * 32 + lane] = acc0;
}

// ---------------- launch ----------------------------------------------------
extern "C" void kernel_launch(void* const* d_in, const int* in_sizes, int n_in,
                              void* d_out, int out_size)
{
    const float* x      = (const float*)d_in[0];
    const int*   eidx   = (const int*)d_in[1];     // [ALPHA, 2, E] (int32 payload)
    const float* eattr  = (const float*)d_in[2];   // [ALPHA, E]
    const float* lin_w  = (const float*)d_in[3];
    const float* lin_b  = (const float*)d_in[4];
    const float* conv_w = (const float*)d_in[5];   // [ALPHA, D, D]
    const float* conv_b = (const float*)d_in[6];   // [ALPHA, D]
    float*       out    = (float*)d_out;           // [ALPHA+1, N, D]

    void* hw_ptr = nullptr;
    cudaGetSymbolAddress(&hw_ptr, g_hwh);

    const int smem_bytes = 4 * TILE_M * LDAH * (int)sizeof(__half);   // 139264
    cudaFuncSetAttribute(gemm_mma, cudaFuncAttributeMaxDynamicSharedMemorySize, smem_bytes);

    const int gemm_blocks      = (N_NODES + TILE_M - 1) / TILE_M;
    const int all_node_blocks  = (ALPHA * N_NODES + 255) / 256;
    const int edge_blocks      = (N_EDGES + 255) / 256;
    const int gather_blocks    = (N_NODES * 32 + 255) / 256;

    // fork: prep chain on side stream, first GEMMs on main stream
    static cudaStream_t sp = nullptr;
    static cudaEvent_t ev_fork = nullptr, ev_join = nullptr;
    if (!sp) {
        cudaStreamCreateWithFlags(&sp, cudaStreamNonBlocking);
        cudaEventCreateWithFlags(&ev_fork, cudaEventDisableTiming);
        cudaEventCreateWithFlags(&ev_join, cudaEventDisableTiming);
    }

    cudaEventRecord(ev_fork, 0);
    cudaStreamWaitEvent(sp, ev_fork, 0);

    clear_kernel<<<all_node_blocks, 256, 0, sp>>>();
    deg_kernel<<<dim3(edge_blocks, ALPHA), 256, 0, sp>>>(eidx, eattr);
    dinv_kernel<<<all_node_blocks, 256, 0, sp>>>();
    scan_p1<<<dim3(NB, ALPHA), SCAN_BLK, 0, sp>>>();
    scan_p2<<<1, 128, 0, sp>>>();
    scan_p3<<<dim3(NB, ALPHA), SCAN_BLK, 0, sp>>>();
    bin_kernel<<<dim3(edge_blocks, ALPHA), 256, 0, sp>>>(eidx, eattr);
    cudaEventRecord(ev_join, sp);

    // main stream: h0 = relu(x @ lin_w.T + lin_b), hw0 — overlap with prep
    gemm_mma<<<gemm_blocks, GT, smem_bytes>>>(x, lin_w, lin_b, out, N_NODES, 1, 0);
    gemm_mma<<<gemm_blocks, GT, smem_bytes>>>(out, conv_w, nullptr, hw_ptr, N_NODES, 0, 1);

    // join: gathers need the CSR from the prep chain
    cudaStreamWaitEvent(0, ev_join, 0);

    for (int i = 0; i < ALPHA; i++) {
        const float* b    = conv_b + (size_t)i * DIM;
        float*       hout = out + (size_t)(i + 1) * N_NODES * DIM;

        gather_kernel<<<gather_blocks, 256>>>(i, b, hout);

        if (i + 1 < ALPHA) {
            const float* Wn = conv_w + (size_t)(i + 1) * DIM * DIM;
            gemm_mma<<<gemm_blocks, GT, smem_bytes>>>(hout, Wn, nullptr, hw_ptr, N_NODES, 0, 1);
        }
    }
}